// round 2
// baseline (speedup 1.0000x reference)
#include <cuda_runtime.h>

// Problem constants
#define NHEADS 16
#define DHEAD  64
#define NTILE  64     // number of q/kv tiles per head
#define TILE   128    // tokens per tile
#define SEQ    8192
#define HID    1024

// Scratch: tiled Q/K/V/O, layout [NH][NTILE][TILE][D]
__device__ float g_q[NHEADS * NTILE * TILE * DHEAD];
__device__ float g_k[NHEADS * NTILE * TILE * DHEAD];
__device__ float g_v[NHEADS * NTILE * TILE * DHEAD];
__device__ float g_o[NHEADS * NTILE * TILE * DHEAD];

// seq index s -> (tile n, within-tile p)
// s = t*1024 + h*32 + w ; t=ntt*2+tt, h=nth*8+th, w=ntw*8+tw
// n = (ntt*4+nth)*4+ntw ; p = (tt*8+th)*8+tw
__device__ __forceinline__ void seq_to_tile(int s, int& n, int& p) {
    int t = s >> 10;
    int h = (s >> 5) & 31;
    int w = s & 31;
    n = (((t >> 1) * 4 + (h >> 3)) * 4 + (w >> 3));
    p = (((t & 1) * 8 + (h & 7)) * 8 + (w & 7));
}

// ---------------------------------------------------------------------------
// QKV projection GEMM: C[s, head*64+d] = X[s,:] @ W[:, head*64+d]
// written directly into tiled layout. 64x64 block, 256 threads, 4x4/thread.
// grid: (HID/64, SEQ/64, 3)   z selects (Wq->g_q, Wk->g_k, Wv->g_v)
// ---------------------------------------------------------------------------
__global__ __launch_bounds__(256) void qkv_gemm(
    const float* __restrict__ X,
    const float* __restrict__ Wq,
    const float* __restrict__ Wk,
    const float* __restrict__ Wv)
{
    const float* W = (blockIdx.z == 0) ? Wq : (blockIdx.z == 1) ? Wk : Wv;
    float* Out = (blockIdx.z == 0) ? g_q : (blockIdx.z == 1) ? g_k : g_v;

    const int m0 = blockIdx.y * 64;
    const int n0 = blockIdx.x * 64;      // one head per n-block (64 == DHEAD)
    const int head = n0 >> 6;

    __shared__ float As[16][65];   // [k][m], padded
    __shared__ float Bs[16][64];   // [k][n]

    const int tid = threadIdx.x;
    const int tx = tid & 15;
    const int ty = tid >> 4;

    float c[4][4] = {};

    for (int kk = 0; kk < HID; kk += 16) {
        #pragma unroll
        for (int l = 0; l < 4; l++) {
            int e = tid + l * 256;
            int m = e >> 4, k = e & 15;
            As[k][m] = X[(m0 + m) * HID + kk + k];
        }
        #pragma unroll
        for (int l = 0; l < 4; l++) {
            int e = tid + l * 256;
            int k = e >> 6, nn = e & 63;
            Bs[k][nn] = W[(kk + k) * HID + n0 + nn];
        }
        __syncthreads();
        #pragma unroll
        for (int k = 0; k < 16; k++) {
            float a[4];
            #pragma unroll
            for (int i = 0; i < 4; i++) a[i] = As[k][ty * 4 + i];
            float4 b = *(const float4*)&Bs[k][tx * 4];
            #pragma unroll
            for (int i = 0; i < 4; i++) {
                c[i][0] += a[i] * b.x;
                c[i][1] += a[i] * b.y;
                c[i][2] += a[i] * b.z;
                c[i][3] += a[i] * b.w;
            }
        }
        __syncthreads();
    }

    #pragma unroll
    for (int i = 0; i < 4; i++) {
        int srow = m0 + ty * 4 + i;
        int n, p;
        seq_to_tile(srow, n, p);
        float4 v = make_float4(c[i][0], c[i][1], c[i][2], c[i][3]);
        *(float4*)&Out[((head * NTILE + n) * TILE + p) * DHEAD + tx * 4] = v;
    }
}

// ---------------------------------------------------------------------------
// Sliding-tile attention. grid = NHEADS*NTILE blocks, 128 threads
// (one query row per thread). K/V streamed in 64-key chunks through smem.
// Online softmax with lazy rescale.
// ---------------------------------------------------------------------------
__global__ __launch_bounds__(128) void attn_kernel()
{
    const int bid = blockIdx.x;
    const int head = bid >> 6;
    const int n = bid & 63;
    const int tid = threadIdx.x;

    __shared__ float4 Ks[64 * 16];   // [key][d4]
    __shared__ float4 Vs[64 * 16];

    const float4* qp = (const float4*)&g_q[((head * NTILE + n) * TILE + tid) * DHEAD];
    float4 q[16];
    #pragma unroll
    for (int i = 0; i < 16; i++) q[i] = qp[i];

    float4 o[16];
    #pragma unroll
    for (int i = 0; i < 16; i++) o[i] = make_float4(0.f, 0.f, 0.f, 0.f);

    float m = -1e30f, l = 0.f;

    // kv window (verified against reference _dim_window):
    // t-dim (nt=4, w=3): center = clip(ntt,1,2), kv_t = center-1+{0,1,2}
    // h/w-dim (nt=4, w=2): center = clip(nt,1,3), kv = center-1+{0,1}
    const int ntt = n >> 4, nth = (n >> 2) & 3, ntw = n & 3;
    const int ct = min(max(ntt, 1), 2);
    const int ch = min(max(nth, 1), 3);
    const int cw = min(max(ntw, 1), 3);

    for (int kk = 0; kk < 12; kk++) {
        const int it = kk >> 2, ih = (kk >> 1) & 1, iw = kk & 1;
        const int kvn = ((ct - 1 + it) * 4 + (ch - 1 + ih)) * 4 + (cw - 1 + iw);
        const float4* kbase = (const float4*)&g_k[((head * NTILE + kvn) * TILE) * DHEAD];
        const float4* vbase = (const float4*)&g_v[((head * NTILE + kvn) * TILE) * DHEAD];

        for (int cchunk = 0; cchunk < 2; cchunk++) {
            __syncthreads();
            #pragma unroll
            for (int r = 0; r < 8; r++) {
                int e = tid + r * 128;          // 1024 float4 = 64 keys x 16
                Ks[e] = kbase[cchunk * 1024 + e];
                Vs[e] = vbase[cchunk * 1024 + e];
            }
            __syncthreads();

            for (int j = 0; j < 64; j++) {
                float s = 0.f;
                #pragma unroll
                for (int d = 0; d < 16; d++) {
                    float4 kv = Ks[j * 16 + d];
                    s += q[d].x * kv.x + q[d].y * kv.y + q[d].z * kv.z + q[d].w * kv.w;
                }
                s *= 0.125f;   // 1/sqrt(64)
                if (s > m) {
                    float corr = __expf(m - s);
                    l *= corr;
                    #pragma unroll
                    for (int d = 0; d < 16; d++) {
                        o[d].x *= corr; o[d].y *= corr; o[d].z *= corr; o[d].w *= corr;
                    }
                    m = s;
                }
                float p = __expf(s - m);
                l += p;
                #pragma unroll
                for (int d = 0; d < 16; d++) {
                    float4 vv = Vs[j * 16 + d];
                    o[d].x += p * vv.x; o[d].y += p * vv.y;
                    o[d].z += p * vv.z; o[d].w += p * vv.w;
                }
            }
        }
    }

    const float inv = 1.f / l;
    float4* op = (float4*)&g_o[((head * NTILE + n) * TILE + tid) * DHEAD];
    #pragma unroll
    for (int i = 0; i < 16; i++) {
        o[i].x *= inv; o[i].y *= inv; o[i].z *= inv; o[i].w *= inv;
        op[i] = o[i];
    }
}

// ---------------------------------------------------------------------------
// Output projection: out[s, :] = O_seq[s, :] @ Wo, where
// O_seq[s, head*64+d] = g_o[head][n(s)][p(s)][d]  (the _from_tiles inverse)
// ---------------------------------------------------------------------------
__global__ __launch_bounds__(256) void oproj_gemm(
    const float* __restrict__ Wo, float* __restrict__ out)
{
    const int m0 = blockIdx.y * 64;
    const int n0 = blockIdx.x * 64;

    __shared__ float As[16][65];
    __shared__ float Bs[16][64];

    const int tid = threadIdx.x;
    const int tx = tid & 15;
    const int ty = tid >> 4;

    float c[4][4] = {};

    for (int kk = 0; kk < HID; kk += 16) {
        #pragma unroll
        for (int l = 0; l < 4; l++) {
            int e = tid + l * 256;
            int m = e >> 4, k = e & 15;
            int srow = m0 + m;
            int n, p;
            seq_to_tile(srow, n, p);
            int kcol = kk + k;
            As[k][m] = g_o[(((kcol >> 6) * NTILE + n) * TILE + p) * DHEAD + (kcol & 63)];
        }
        #pragma unroll
        for (int l = 0; l < 4; l++) {
            int e = tid + l * 256;
            int k = e >> 6, nn = e & 63;
            Bs[k][nn] = Wo[(kk + k) * HID + n0 + nn];
        }
        __syncthreads();
        #pragma unroll
        for (int k = 0; k < 16; k++) {
            float a[4];
            #pragma unroll
            for (int i = 0; i < 4; i++) a[i] = As[k][ty * 4 + i];
            float4 b = *(const float4*)&Bs[k][tx * 4];
            #pragma unroll
            for (int i = 0; i < 4; i++) {
                c[i][0] += a[i] * b.x;
                c[i][1] += a[i] * b.y;
                c[i][2] += a[i] * b.z;
                c[i][3] += a[i] * b.w;
            }
        }
        __syncthreads();
    }

    #pragma unroll
    for (int i = 0; i < 4; i++) {
        int srow = m0 + ty * 4 + i;
        float4 v = make_float4(c[i][0], c[i][1], c[i][2], c[i][3]);
        *(float4*)&out[srow * HID + n0 + tx * 4] = v;
    }
}

extern "C" void kernel_launch(void* const* d_in, const int* in_sizes, int n_in,
                              void* d_out, int out_size)
{
    const float* X  = (const float*)d_in[0];
    const float* Wq = (const float*)d_in[1];
    const float* Wk = (const float*)d_in[2];
    const float* Wv = (const float*)d_in[3];
    const float* Wo = (const float*)d_in[4];
    float* out = (float*)d_out;

    dim3 gqkv(HID / 64, SEQ / 64, 3);
    qkv_gemm<<<gqkv, 256>>>(X, Wq, Wk, Wv);

    attn_kernel<<<NHEADS * NTILE, 128>>>();

    dim3 gop(HID / 64, SEQ / 64, 1);
    oproj_gemm<<<gop, 256>>>(Wo, out);
}

// round 3
// speedup vs baseline: 3.6979x; 3.6979x over previous
#include <cuda_runtime.h>

// Problem constants
#define NHEADS 16
#define DHEAD  64
#define NTILE  64     // q/kv tiles per head
#define TILE   128    // tokens per tile
#define SEQ    8192
#define HID    1024

// Scratch: tiled Q/K/V/O, layout [NH][NTILE][TILE][D], values tf32-rounded
__device__ float g_q[NHEADS * NTILE * TILE * DHEAD];
__device__ float g_k[NHEADS * NTILE * TILE * DHEAD];
__device__ float g_v[NHEADS * NTILE * TILE * DHEAD];
__device__ float g_o[NHEADS * NTILE * TILE * DHEAD];

// seq index s -> (tile n, within-tile p)
__device__ __forceinline__ void seq_to_tile(int s, int& n, int& p) {
    int t = s >> 10;
    int h = (s >> 5) & 31;
    int w = s & 31;
    n = (((t >> 1) * 4 + (h >> 3)) * 4 + (w >> 3));
    p = (((t & 1) * 8 + (h & 7)) * 8 + (w & 7));
}

__device__ __forceinline__ unsigned f2tf32(float x) {
    unsigned u;
    asm("cvt.rna.tf32.f32 %0, %1;" : "=r"(u) : "f"(x));
    return u;
}
__device__ __forceinline__ float tff(float x) { return __uint_as_float(f2tf32(x)); }

__device__ __forceinline__ float ex2(float x) {
    float y;
    asm("ex2.approx.f32 %0, %1;" : "=f"(y) : "f"(x));
    return y;
}

// D = A(16x8 row) * B(8x8 col) + D, tf32
__device__ __forceinline__ void mma_tf32(float& c0, float& c1, float& c2, float& c3,
                                         unsigned a0, unsigned a1, unsigned a2, unsigned a3,
                                         unsigned b0, unsigned b1) {
    asm volatile(
        "mma.sync.aligned.m16n8k8.row.col.f32.tf32.tf32.f32 "
        "{%0,%1,%2,%3},{%4,%5,%6,%7},{%8,%9},{%0,%1,%2,%3};"
        : "+f"(c0), "+f"(c1), "+f"(c2), "+f"(c3)
        : "r"(a0), "r"(a1), "r"(a2), "r"(a3), "r"(b0), "r"(b1));
}

// ---------------------------------------------------------------------------
// QKV projection: 128x64 block tile, 4 warps (2x2), warp tile 64x32, K-chunk 32.
// grid (16, 64, 3): x = head (n0 = head*64), y = m-block, z selects Q/K/V.
// Epilogue writes tf32-rounded values into tiled layout.
// ---------------------------------------------------------------------------
__global__ __launch_bounds__(128) void qkv_gemm(
    const float* __restrict__ X,
    const float* __restrict__ Wq,
    const float* __restrict__ Wk,
    const float* __restrict__ Wv)
{
    const float* W = (blockIdx.z == 0) ? Wq : (blockIdx.z == 1) ? Wk : Wv;
    float* Out = (blockIdx.z == 0) ? g_q : (blockIdx.z == 1) ? g_k : g_v;

    const int m0 = blockIdx.y * 128;
    const int head = blockIdx.x;
    const int n0 = head * 64;

    __shared__ float As[128 * 36];   // [m][k], stride 36 (conflict-free frag LDS)
    __shared__ float Bs[32 * 72];    // [k][n], stride 72

    const int tid = threadIdx.x;
    const int warp = tid >> 5, lane = tid & 31;
    const int g = lane >> 2, c = lane & 3;
    const int wm = warp >> 1, wn = warp & 1;

    float acc[4][4][4] = {};

    for (int kk = 0; kk < HID; kk += 32) {
        #pragma unroll
        for (int l = 0; l < 8; l++) {
            int e = tid + l * 128;
            int row = e >> 3, c4 = e & 7;
            float4 v = *(const float4*)&X[(m0 + row) * HID + kk + c4 * 4];
            v.x = tff(v.x); v.y = tff(v.y); v.z = tff(v.z); v.w = tff(v.w);
            *(float4*)&As[row * 36 + c4 * 4] = v;
        }
        #pragma unroll
        for (int l = 0; l < 4; l++) {
            int e = tid + l * 128;
            int k = e >> 4, c4 = e & 15;
            float4 v = *(const float4*)&W[(kk + k) * HID + n0 + c4 * 4];
            v.x = tff(v.x); v.y = tff(v.y); v.z = tff(v.z); v.w = tff(v.w);
            *(float4*)&Bs[k * 72 + c4 * 4] = v;
        }
        __syncthreads();

        #pragma unroll
        for (int ks = 0; ks < 4; ks++) {
            unsigned a[4][4], b[4][2];
            #pragma unroll
            for (int mf = 0; mf < 4; mf++) {
                const float* p = &As[(wm * 64 + mf * 16 + g) * 36 + ks * 8 + c];
                a[mf][0] = __float_as_uint(p[0]);
                a[mf][1] = __float_as_uint(p[8 * 36]);
                a[mf][2] = __float_as_uint(p[4]);
                a[mf][3] = __float_as_uint(p[8 * 36 + 4]);
            }
            #pragma unroll
            for (int nf = 0; nf < 4; nf++) {
                int col = wn * 32 + nf * 8 + g;
                b[nf][0] = __float_as_uint(Bs[(ks * 8 + c) * 72 + col]);
                b[nf][1] = __float_as_uint(Bs[(ks * 8 + c + 4) * 72 + col]);
            }
            #pragma unroll
            for (int mf = 0; mf < 4; mf++)
                #pragma unroll
                for (int nf = 0; nf < 4; nf++)
                    mma_tf32(acc[mf][nf][0], acc[mf][nf][1], acc[mf][nf][2], acc[mf][nf][3],
                             a[mf][0], a[mf][1], a[mf][2], a[mf][3], b[nf][0], b[nf][1]);
        }
        __syncthreads();
    }

    #pragma unroll
    for (int mf = 0; mf < 4; mf++) {
        int r0 = m0 + wm * 64 + mf * 16 + g;
        int r1 = r0 + 8;
        int n_, p_, n2, p2;
        seq_to_tile(r0, n_, p_);
        seq_to_tile(r1, n2, p2);
        #pragma unroll
        for (int nf = 0; nf < 4; nf++) {
            int col = wn * 32 + nf * 8 + 2 * c;
            float2 v0 = make_float2(tff(acc[mf][nf][0]), tff(acc[mf][nf][1]));
            float2 v1 = make_float2(tff(acc[mf][nf][2]), tff(acc[mf][nf][3]));
            *(float2*)&Out[((head * NTILE + n_) * TILE + p_) * DHEAD + col] = v0;
            *(float2*)&Out[((head * NTILE + n2) * TILE + p2) * DHEAD + col] = v1;
        }
    }
}

// ---------------------------------------------------------------------------
// Flash attention over the tile window. 1 block per (head, q-tile): 1024 blocks,
// 256 threads = 8 warps; warp w owns q rows 16w..16w+15 (softmax stays in-warp).
// KV streamed in 32-key chunks; S and PV via tf32 mma; P round-trips via smem.
// ---------------------------------------------------------------------------
__global__ __launch_bounds__(256) void attn_kernel()
{
    const int bid = blockIdx.x;
    const int head = bid >> 6;
    const int n = bid & 63;
    const int tid = threadIdx.x;
    const int warp = tid >> 5, lane = tid & 31;
    const int g = lane >> 2, c = lane & 3;

    __shared__ float Ks[32 * 72];    // [key][d], stride 72
    __shared__ float Vs[32 * 72];
    __shared__ float Ps[128 * 36];   // [q][key-chunk], stride 36

    // Q fragments (pre-scaled by 1/sqrt(D) * log2e, tf32)
    const float SC = 0.125f * 1.4426950408889634f;
    unsigned Qf[8][4];
    {
        const float* qb = &g_q[(size_t)((head * NTILE + n) * TILE) * DHEAD];
        int r = warp * 16 + g;
        #pragma unroll
        for (int kf = 0; kf < 8; kf++) {
            int col = kf * 8 + c;
            Qf[kf][0] = f2tf32(qb[r * 64 + col] * SC);
            Qf[kf][1] = f2tf32(qb[(r + 8) * 64 + col] * SC);
            Qf[kf][2] = f2tf32(qb[r * 64 + col + 4] * SC);
            Qf[kf][3] = f2tf32(qb[(r + 8) * 64 + col + 4] * SC);
        }
    }

    float O[8][4] = {};
    float m0 = -1e30f, m1 = -1e30f, l0 = 0.f, l1 = 0.f;

    // kv window: t-dim (nt=4,w=3): center=clip(ntt,1,2); h/w (nt=4,w=2): center=clip(.,1,3)
    const int ntt = n >> 4, nth = (n >> 2) & 3, ntw = n & 3;
    const int ct = min(max(ntt, 1), 2);
    const int ch = min(max(nth, 1), 3);
    const int cw = min(max(ntw, 1), 3);

    for (int kk = 0; kk < 12; kk++) {
        const int it = kk >> 2, ih = (kk >> 1) & 1, iw = kk & 1;
        const int kvn = ((ct - 1 + it) * 4 + (ch - 1 + ih)) * 4 + (cw - 1 + iw);
        const float* kb = &g_k[(size_t)((head * NTILE + kvn) * TILE) * DHEAD];
        const float* vb = &g_v[(size_t)((head * NTILE + kvn) * TILE) * DHEAD];

        for (int cc = 0; cc < 4; cc++) {
            __syncthreads();
            #pragma unroll
            for (int l2 = 0; l2 < 2; l2++) {
                int e = tid + l2 * 256;
                int key = e >> 4, c4 = e & 15;
                *(float4*)&Ks[key * 72 + c4 * 4] =
                    *(const float4*)&kb[(cc * 32 + key) * 64 + c4 * 4];
                *(float4*)&Vs[key * 72 + c4 * 4] =
                    *(const float4*)&vb[(cc * 32 + key) * 64 + c4 * 4];
            }
            __syncthreads();

            // S = Q * K^T (scaled): 16 rows x 32 keys per warp
            float S[4][4] = {};
            #pragma unroll
            for (int ks = 0; ks < 8; ks++) {
                unsigned b0[4], b1[4];
                #pragma unroll
                for (int nf = 0; nf < 4; nf++) {
                    int key = nf * 8 + g;
                    b0[nf] = __float_as_uint(Ks[key * 72 + ks * 8 + c]);
                    b1[nf] = __float_as_uint(Ks[key * 72 + ks * 8 + c + 4]);
                }
                #pragma unroll
                for (int nf = 0; nf < 4; nf++)
                    mma_tf32(S[nf][0], S[nf][1], S[nf][2], S[nf][3],
                             Qf[ks][0], Qf[ks][1], Qf[ks][2], Qf[ks][3], b0[nf], b1[nf]);
            }

            // online softmax (rows r=16w+g and r+8; 4 lanes per row)
            float rmax0 = -1e30f, rmax1 = -1e30f;
            #pragma unroll
            for (int nf = 0; nf < 4; nf++) {
                rmax0 = fmaxf(rmax0, fmaxf(S[nf][0], S[nf][1]));
                rmax1 = fmaxf(rmax1, fmaxf(S[nf][2], S[nf][3]));
            }
            rmax0 = fmaxf(rmax0, __shfl_xor_sync(0xffffffffu, rmax0, 1));
            rmax0 = fmaxf(rmax0, __shfl_xor_sync(0xffffffffu, rmax0, 2));
            rmax1 = fmaxf(rmax1, __shfl_xor_sync(0xffffffffu, rmax1, 1));
            rmax1 = fmaxf(rmax1, __shfl_xor_sync(0xffffffffu, rmax1, 2));

            float mn0 = fmaxf(m0, rmax0), mn1 = fmaxf(m1, rmax1);
            float sf0 = ex2(m0 - mn0), sf1 = ex2(m1 - mn1);

            float rs0 = 0.f, rs1 = 0.f;
            #pragma unroll
            for (int nf = 0; nf < 4; nf++) {
                S[nf][0] = ex2(S[nf][0] - mn0);
                S[nf][1] = ex2(S[nf][1] - mn0);
                S[nf][2] = ex2(S[nf][2] - mn1);
                S[nf][3] = ex2(S[nf][3] - mn1);
                rs0 += S[nf][0] + S[nf][1];
                rs1 += S[nf][2] + S[nf][3];
            }
            rs0 += __shfl_xor_sync(0xffffffffu, rs0, 1);
            rs0 += __shfl_xor_sync(0xffffffffu, rs0, 2);
            rs1 += __shfl_xor_sync(0xffffffffu, rs1, 1);
            rs1 += __shfl_xor_sync(0xffffffffu, rs1, 2);

            l0 = l0 * sf0 + rs0;
            l1 = l1 * sf1 + rs1;
            m0 = mn0; m1 = mn1;

            #pragma unroll
            for (int nf = 0; nf < 8; nf++) {
                O[nf][0] *= sf0; O[nf][1] *= sf0;
                O[nf][2] *= sf1; O[nf][3] *= sf1;
            }

            // P -> smem (tf32), re-fragment as mma A
            {
                int r = warp * 16 + g;
                #pragma unroll
                for (int nf = 0; nf < 4; nf++) {
                    *(float2*)&Ps[r * 36 + nf * 8 + 2 * c] =
                        make_float2(tff(S[nf][0]), tff(S[nf][1]));
                    *(float2*)&Ps[(r + 8) * 36 + nf * 8 + 2 * c] =
                        make_float2(tff(S[nf][2]), tff(S[nf][3]));
                }
            }
            __syncwarp();

            // O += P * V
            {
                int r = warp * 16 + g;
                #pragma unroll
                for (int ko = 0; ko < 4; ko++) {
                    unsigned pa0 = __float_as_uint(Ps[r * 36 + ko * 8 + c]);
                    unsigned pa1 = __float_as_uint(Ps[(r + 8) * 36 + ko * 8 + c]);
                    unsigned pa2 = __float_as_uint(Ps[r * 36 + ko * 8 + c + 4]);
                    unsigned pa3 = __float_as_uint(Ps[(r + 8) * 36 + ko * 8 + c + 4]);
                    #pragma unroll
                    for (int nf = 0; nf < 8; nf++) {
                        unsigned vb0 = __float_as_uint(Vs[(ko * 8 + c) * 72 + nf * 8 + g]);
                        unsigned vb1 = __float_as_uint(Vs[(ko * 8 + c + 4) * 72 + nf * 8 + g]);
                        mma_tf32(O[nf][0], O[nf][1], O[nf][2], O[nf][3],
                                 pa0, pa1, pa2, pa3, vb0, vb1);
                    }
                }
            }
        }
    }

    const float inv0 = 1.f / l0, inv1 = 1.f / l1;
    float* ob = &g_o[(size_t)((head * NTILE + n) * TILE) * DHEAD];
    int r = warp * 16 + g;
    #pragma unroll
    for (int nf = 0; nf < 8; nf++) {
        int col = nf * 8 + 2 * c;
        *(float2*)&ob[r * 64 + col] =
            make_float2(tff(O[nf][0] * inv0), tff(O[nf][1] * inv0));
        *(float2*)&ob[(r + 8) * 64 + col] =
            make_float2(tff(O[nf][2] * inv1), tff(O[nf][3] * inv1));
    }
}

// ---------------------------------------------------------------------------
// Output projection: out = O_seq @ Wo with _from_tiles remap fused into A fill.
// Same tiling as qkv_gemm. grid (16, 64).
// ---------------------------------------------------------------------------
__global__ __launch_bounds__(128) void oproj_gemm(
    const float* __restrict__ Wo, float* __restrict__ out)
{
    const int m0 = blockIdx.y * 128;
    const int n0 = blockIdx.x * 64;

    __shared__ float As[128 * 36];
    __shared__ float Bs[32 * 72];

    const int tid = threadIdx.x;
    const int warp = tid >> 5, lane = tid & 31;
    const int g = lane >> 2, c = lane & 3;
    const int wm = warp >> 1, wn = warp & 1;

    float acc[4][4][4] = {};

    for (int kk = 0; kk < HID; kk += 32) {
        const int hk = kk >> 6;          // head for this k-chunk (32 | 64)
        const int dbase = kk & 63;       // 0 or 32
        #pragma unroll
        for (int l = 0; l < 8; l++) {
            int e = tid + l * 128;
            int row = e >> 3, c4 = e & 7;
            int nn, pp;
            seq_to_tile(m0 + row, nn, pp);
            float4 v = *(const float4*)&g_o[((size_t)((hk * NTILE + nn) * TILE + pp)) * DHEAD
                                            + dbase + c4 * 4];
            // g_o already tf32-rounded
            *(float4*)&As[row * 36 + c4 * 4] = v;
        }
        #pragma unroll
        for (int l = 0; l < 4; l++) {
            int e = tid + l * 128;
            int k = e >> 4, c4 = e & 15;
            float4 v = *(const float4*)&Wo[(kk + k) * HID + n0 + c4 * 4];
            v.x = tff(v.x); v.y = tff(v.y); v.z = tff(v.z); v.w = tff(v.w);
            *(float4*)&Bs[k * 72 + c4 * 4] = v;
        }
        __syncthreads();

        #pragma unroll
        for (int ks = 0; ks < 4; ks++) {
            unsigned a[4][4], b[4][2];
            #pragma unroll
            for (int mf = 0; mf < 4; mf++) {
                const float* p = &As[(wm * 64 + mf * 16 + g) * 36 + ks * 8 + c];
                a[mf][0] = __float_as_uint(p[0]);
                a[mf][1] = __float_as_uint(p[8 * 36]);
                a[mf][2] = __float_as_uint(p[4]);
                a[mf][3] = __float_as_uint(p[8 * 36 + 4]);
            }
            #pragma unroll
            for (int nf = 0; nf < 4; nf++) {
                int col = wn * 32 + nf * 8 + g;
                b[nf][0] = __float_as_uint(Bs[(ks * 8 + c) * 72 + col]);
                b[nf][1] = __float_as_uint(Bs[(ks * 8 + c + 4) * 72 + col]);
            }
            #pragma unroll
            for (int mf = 0; mf < 4; mf++)
                #pragma unroll
                for (int nf = 0; nf < 4; nf++)
                    mma_tf32(acc[mf][nf][0], acc[mf][nf][1], acc[mf][nf][2], acc[mf][nf][3],
                             a[mf][0], a[mf][1], a[mf][2], a[mf][3], b[nf][0], b[nf][1]);
        }
        __syncthreads();
    }

    #pragma unroll
    for (int mf = 0; mf < 4; mf++) {
        int r0 = m0 + wm * 64 + mf * 16 + g;
        int r1 = r0 + 8;
        #pragma unroll
        for (int nf = 0; nf < 4; nf++) {
            int col = n0 + wn * 32 + nf * 8 + 2 * c;
            *(float2*)&out[r0 * HID + col] = make_float2(acc[mf][nf][0], acc[mf][nf][1]);
            *(float2*)&out[r1 * HID + col] = make_float2(acc[mf][nf][2], acc[mf][nf][3]);
        }
    }
}

extern "C" void kernel_launch(void* const* d_in, const int* in_sizes, int n_in,
                              void* d_out, int out_size)
{
    const float* X  = (const float*)d_in[0];
    const float* Wq = (const float*)d_in[1];
    const float* Wk = (const float*)d_in[2];
    const float* Wv = (const float*)d_in[3];
    const float* Wo = (const float*)d_in[4];
    float* out = (float*)d_out;

    dim3 gqkv(16, 64, 3);
    qkv_gemm<<<gqkv, 128>>>(X, Wq, Wk, Wv);

    attn_kernel<<<NHEADS * NTILE, 256>>>();

    dim3 gop(16, 64);
    oproj_gemm<<<gop, 128>>>(Wo, out);
}